// round 15
// baseline (speedup 1.0000x reference)
#include <cuda_runtime.h>
#include <cuda_bf16.h>
#include <math.h>

#define BATCH 32
#define HDIM 112
#define WDIM 112
#define CDIM 192
#define HW (HDIM*WDIM)          // 12544
#define C4 (CDIM/4)             // 48

// ---------------- scratch (device globals; no allocation) ----------------
__device__ float    g_sum[BATCH*CDIM];          // spatial sum per (b,c)
__device__ unsigned g_maxu[BATCH*CDIM];         // spatial max per (b,c), ordered-uint
__device__ float    g_scale[BATCH*CDIM];        // fused se*channel_att per (b,c)
__device__ float2   g_sp[BATCH*HW];             // per-pixel {avg_c, max_c}

__device__ __forceinline__ unsigned f2u_ord(float f) {
    unsigned u = __float_as_uint(f);
    return (u & 0x80000000u) ? ~u : (u | 0x80000000u);
}
__device__ __forceinline__ float u2f_ord(unsigned u) {
    return (u & 0x80000000u) ? __uint_as_float(u & 0x7fffffffu) : __uint_as_float(~u);
}
__device__ __forceinline__ float sigm(float v) { return 1.0f / (1.0f + expf(-v)); }
__device__ __forceinline__ float swishf(float v) { return v * sigm(v); }

// ---------------- kernel 0: init accumulators ----------------
__global__ void k_init() {
    int i = blockIdx.x * 256 + threadIdx.x;
    if (i < BATCH*CDIM) { g_sum[i] = 0.0f; g_maxu[i] = 0u; }
}

// ---------------- kernel 1: fused pools (one pass over x) ----------------
// grid (56, B), block 256 (8 warps). Each block = TWO image rows (224 px).
// Warp handles 28 pixels as 7 groups of 4 with software prefetch (group
// i+1's 12 float2 loads issue before group i's reduction). Per-pixel warp
// reductions use a PAIRED butterfly: pixels (A,B) share one tree -- lanes
// <16 reduce A, lanes >=16 reduce B after a single xor-16 fold. 20 shuffles
// per 4-pixel group instead of 40 (sm_103 has no redux.sync.f32).
__global__ void __launch_bounds__(256, 4) k_pool(const float* __restrict__ x) {
    int b = blockIdx.y;
    int h0 = blockIdx.x * 2;
    int warp = threadIdx.x >> 5, lane = threadIdx.x & 31;

    __shared__ float    s_sum[CDIM];
    __shared__ unsigned s_max[CDIM];
    if (threadIdx.x < CDIM) { s_sum[threadIdx.x] = 0.0f; s_max[threadIdx.x] = 0u; }
    __syncthreads();

    float csum[6] = {0.f,0.f,0.f,0.f,0.f,0.f};
    float cmax[6] = {-3.4e38f,-3.4e38f,-3.4e38f,-3.4e38f,-3.4e38f,-3.4e38f};

    const float* xbase = x + (size_t)(b*HW + h0*WDIM) * CDIM;   // 224 pixels
    float2* spbase = g_sp + b*HW + h0*WDIM;

    float2 cur[12];
    int p = warp * 4;
    #pragma unroll
    for (int q = 0; q < 4; q++)
        #pragma unroll
        for (int j = 0; j < 3; j++)
            cur[q*3+j] = __ldcs((const float2*)(xbase + (size_t)(p+q)*CDIM) + lane + 32*j);

    #pragma unroll
    for (int it = 0; it < 7; it++) {
        float2 nxt[12];
        int pn = p + 32;
        if (it < 6) {
            #pragma unroll
            for (int q = 0; q < 4; q++)
                #pragma unroll
                for (int j = 0; j < 3; j++)
                    nxt[q*3+j] = __ldcs((const float2*)(xbase + (size_t)(pn+q)*CDIM) + lane + 32*j);
        }

        float ps[4], pm[4];
        #pragma unroll
        for (int q = 0; q < 4; q++) {
            float2 v0 = cur[q*3], v1 = cur[q*3+1], v2 = cur[q*3+2];
            csum[0] += v0.x; csum[1] += v0.y;
            csum[2] += v1.x; csum[3] += v1.y;
            csum[4] += v2.x; csum[5] += v2.y;
            cmax[0] = fmaxf(cmax[0], v0.x); cmax[1] = fmaxf(cmax[1], v0.y);
            cmax[2] = fmaxf(cmax[2], v1.x); cmax[3] = fmaxf(cmax[3], v1.y);
            cmax[4] = fmaxf(cmax[4], v2.x); cmax[5] = fmaxf(cmax[5], v2.y);
            ps[q] = (v0.x + v0.y) + (v1.x + v1.y) + (v2.x + v2.y);
            pm[q] = fmaxf(fmaxf(fmaxf(v0.x,v0.y), fmaxf(v1.x,v1.y)), fmaxf(v2.x,v2.y));
        }

        // paired reductions: (ps0,ps1) and (ps2,ps3) each share one tree
        bool lo = (lane < 16);
        #pragma unroll
        for (int pr2 = 0; pr2 < 2; pr2++) {
            float a  = ps[2*pr2], bv = ps[2*pr2+1];
            float v  = lo ? a  : bv;
            float w  = lo ? bv : a;
            v += __shfl_xor_sync(0xffffffffu, w, 16);
            float ma = pm[2*pr2], mb = pm[2*pr2+1];
            float mv = lo ? ma : mb;
            float mw = lo ? mb : ma;
            mv = fmaxf(mv, __shfl_xor_sync(0xffffffffu, mw, 16));
            #pragma unroll
            for (int o = 8; o > 0; o >>= 1) {
                v += __shfl_xor_sync(0xffffffffu, v, o);
                mv = fmaxf(mv, __shfl_xor_sync(0xffffffffu, mv, o));
            }
            // lane 0 holds pixel A totals, lane 16 holds pixel B totals
            if (lane == 0)  spbase[p+2*pr2]   = make_float2(v * (1.0f/192.0f), mv);
            if (lane == 16) spbase[p+2*pr2+1] = make_float2(v * (1.0f/192.0f), mv);
        }

        #pragma unroll
        for (int k = 0; k < 12; k++) cur[k] = nxt[k];
        p = pn;
    }

    #pragma unroll
    for (int j = 0; j < 3; j++) {
        int c = 2*(lane + 32*j);
        atomicAdd(&s_sum[c],   csum[2*j]);
        atomicAdd(&s_sum[c+1], csum[2*j+1]);
        atomicMax(&s_max[c],   f2u_ord(cmax[2*j]));
        atomicMax(&s_max[c+1], f2u_ord(cmax[2*j+1]));
    }
    __syncthreads();
    if (threadIdx.x < CDIM) {
        atomicAdd(&g_sum[b*CDIM + threadIdx.x], s_sum[threadIdx.x]);
        atomicMax(&g_maxu[b*CDIM + threadIdx.x], s_max[threadIdx.x]);
    }
}

// ---------------- kernel 2: SE + CBAM-channel MLPs, fused scale ----------------
// grid B, block 192
__global__ void k_mlp(const float* __restrict__ se_w1, const float* __restrict__ se_b1,
                      const float* __restrict__ se_w2, const float* __restrict__ se_b2,
                      const float* __restrict__ mlp_w1, const float* __restrict__ mlp_b1,
                      const float* __restrict__ mlp_w2, const float* __restrict__ mlp_b2) {
    int b = blockIdx.x, t = threadIdx.x;
    __shared__ float avg[CDIM], mx[CDIM], hse[12], ha[24], hm[24];

    avg[t] = g_sum[b*CDIM + t] * (1.0f/(float)HW);
    mx[t]  = u2f_ord(g_maxu[b*CDIM + t]);
    __syncthreads();

    if (t < 12) {
        float a = se_b1[t];
        for (int c = 0; c < CDIM; c++) a += avg[c] * se_w1[c*12 + t];
        hse[t] = swishf(a);
    } else if (t >= 32 && t < 56) {
        int j = t - 32;
        float a = mlp_b1[j], m = mlp_b1[j];
        for (int c = 0; c < CDIM; c++) {
            float w = mlp_w1[c*24 + j];
            a += avg[c]*w; m += mx[c]*w;
        }
        ha[j] = swishf(a); hm[j] = swishf(m);
    }
    __syncthreads();

    float s = se_b2[t];
    #pragma unroll
    for (int j = 0; j < 12; j++) s += hse[j] * se_w2[j*CDIM + t];
    float catt = 2.0f * mlp_b2[t];
    #pragma unroll
    for (int j = 0; j < 24; j++) catt += (ha[j] + hm[j]) * mlp_w2[j*CDIM + t];

    g_scale[b*CDIM + t] = sigm(s) * sigm(catt);
}

// ---------------- kernel 3: fused 7x7 conv + sigmoid + elementwise apply ----
// grid (H, B), block (48, 8) = 384 threads. Per block: 7x118 float2 tile of
// g_sp (L2-hot), 112 threads compute the row's spatial attention into smem,
// then all 384 threads stream x -> out with float4 evict-first. Fused conv
// costs ~5us chip-wide hidden under the DRAM stream (R7: 93.4us fused vs
// R12/R13 split: 88 + 13.7).
__global__ void k_apply(const float* __restrict__ x, float* __restrict__ out,
                        const float* __restrict__ conv_k, const float* __restrict__ conv_b) {
    int b = blockIdx.y, h = blockIdx.x;
    int tid = threadIdx.y * C4 + threadIdx.x;

    __shared__ float2 tile[7][WDIM+6];     // rows h-3..h+3, cols -3..114
    __shared__ float  sa[WDIM];
    __shared__ float2 kk2[49];
    __shared__ float  kb;

    for (int i = tid; i < 7*(WDIM+6); i += 384) {
        int kh = i / (WDIM+6);
        int ww = i - kh*(WDIM+6);
        int gh = h + kh - 3, gw = ww - 3;
        float2 v = make_float2(0.0f, 0.0f);
        if (gh >= 0 && gh < HDIM && gw >= 0 && gw < WDIM)
            v = g_sp[b*HW + gh*WDIM + gw];
        tile[kh][ww] = v;
    }
    if (tid < 49) kk2[tid] = ((const float2*)conv_k)[tid];
    if (tid == 0) kb = conv_b[0];
    __syncthreads();

    if (tid < WDIM) {
        float acc = kb;
        #pragma unroll
        for (int kh = 0; kh < 7; kh++)
            #pragma unroll
            for (int kw = 0; kw < 7; kw++) {
                float2 v = tile[kh][tid+kw];
                float2 k = kk2[kh*7+kw];
                acc += v.x * k.x + v.y * k.y;
            }
        sa[tid] = sigm(acc);
    }
    __syncthreads();

    int c4 = threadIdx.x, ty = threadIdx.y;
    float4 sc = ((const float4*)(g_scale + b*CDIM))[c4];
    const float4* xp = (const float4*)x + (size_t)(b*HW + h*WDIM) * C4;
    float4*       op = (float4*)out     + (size_t)(b*HW + h*WDIM) * C4;

    #pragma unroll 7
    for (int p = ty; p < WDIM; p += 8) {
        float s = sa[p];
        float4 v = __ldcs(xp + p*C4 + c4);
        v.x *= sc.x * s; v.y *= sc.y * s;
        v.z *= sc.z * s; v.w *= sc.w * s;
        __stcs(op + p*C4 + c4, v);
    }
}

// ---------------- launch ----------------
extern "C" void kernel_launch(void* const* d_in, const int* in_sizes, int n_in,
                              void* d_out, int out_size) {
    const float* x      = (const float*)d_in[0];
    const float* se_w1  = (const float*)d_in[1];
    const float* se_b1  = (const float*)d_in[2];
    const float* se_w2  = (const float*)d_in[3];
    const float* se_b2  = (const float*)d_in[4];
    const float* mlp_w1 = (const float*)d_in[5];
    const float* mlp_b1 = (const float*)d_in[6];
    const float* mlp_w2 = (const float*)d_in[7];
    const float* mlp_b2 = (const float*)d_in[8];
    const float* conv_k = (const float*)d_in[9];
    const float* conv_b = (const float*)d_in[10];
    float* out = (float*)d_out;

    k_init<<<(BATCH*CDIM + 255)/256, 256>>>();
    k_pool<<<dim3(HDIM/2, BATCH), 256>>>(x);
    k_mlp<<<BATCH, CDIM>>>(se_w1, se_b1, se_w2, se_b2, mlp_w1, mlp_b1, mlp_w2, mlp_b2);
    k_apply<<<dim3(HDIM, BATCH), dim3(C4, 8)>>>(x, out, conv_k, conv_b);
}

// round 16
// speedup vs baseline: 1.1995x; 1.1995x over previous
#include <cuda_runtime.h>
#include <cuda_bf16.h>
#include <math.h>

#define BATCH 32
#define HDIM 112
#define WDIM 112
#define CDIM 192
#define HW (HDIM*WDIM)          // 12544
#define C4 (CDIM/4)             // 48

// ---------------- scratch (device globals; no allocation) ----------------
__device__ float    g_sum[BATCH*CDIM];          // spatial sum per (b,c)
__device__ unsigned g_maxu[BATCH*CDIM];         // spatial max per (b,c), ordered-uint
__device__ float    g_scale[BATCH*CDIM];        // fused se*channel_att per (b,c)
__device__ float2   g_sp[BATCH*HW];             // per-pixel {avg_c, max_c}

__device__ __forceinline__ unsigned f2u_ord(float f) {
    unsigned u = __float_as_uint(f);
    return (u & 0x80000000u) ? ~u : (u | 0x80000000u);
}
__device__ __forceinline__ float u2f_ord(unsigned u) {
    return (u & 0x80000000u) ? __uint_as_float(u & 0x7fffffffu) : __uint_as_float(~u);
}
__device__ __forceinline__ float sigm(float v) { return 1.0f / (1.0f + expf(-v)); }
__device__ __forceinline__ float swishf(float v) { return v * sigm(v); }

// ---------------- kernel 0: init accumulators ----------------
__global__ void k_init() {
    int i = blockIdx.x * 256 + threadIdx.x;
    if (i < BATCH*CDIM) { g_sum[i] = 0.0f; g_maxu[i] = 0u; }
}

// ---------------- kernel 1: fused pools (one pass over x) ----------------
// EXACT R8 structure (measured ~62us): grid (56, B), block 256 (8 warps),
// two rows/block, warps process 4-pixel groups with software prefetch
// (group i+1's 12 float2 loads issue before group i's butterfly), plain
// 5-step shuffle butterfly per pixel.
__global__ void __launch_bounds__(256, 4) k_pool(const float* __restrict__ x) {
    int b = blockIdx.y;
    int h0 = blockIdx.x * 2;
    int warp = threadIdx.x >> 5, lane = threadIdx.x & 31;

    __shared__ float    s_sum[CDIM];
    __shared__ unsigned s_max[CDIM];
    if (threadIdx.x < CDIM) { s_sum[threadIdx.x] = 0.0f; s_max[threadIdx.x] = 0u; }
    __syncthreads();

    float csum[6] = {0.f,0.f,0.f,0.f,0.f,0.f};
    float cmax[6] = {-3.4e38f,-3.4e38f,-3.4e38f,-3.4e38f,-3.4e38f,-3.4e38f};

    const float* xbase = x + (size_t)(b*HW + h0*WDIM) * CDIM;   // 224 pixels
    float2* spbase = g_sp + b*HW + h0*WDIM;

    float2 cur[12];
    int p = warp * 4;
    #pragma unroll
    for (int q = 0; q < 4; q++)
        #pragma unroll
        for (int j = 0; j < 3; j++)
            cur[q*3+j] = __ldcs((const float2*)(xbase + (size_t)(p+q)*CDIM) + lane + 32*j);

    #pragma unroll
    for (int it = 0; it < 7; it++) {
        float2 nxt[12];
        int pn = p + 32;
        if (it < 6) {
            #pragma unroll
            for (int q = 0; q < 4; q++)
                #pragma unroll
                for (int j = 0; j < 3; j++)
                    nxt[q*3+j] = __ldcs((const float2*)(xbase + (size_t)(pn+q)*CDIM) + lane + 32*j);
        }

        float ps[4], pm[4];
        #pragma unroll
        for (int q = 0; q < 4; q++) {
            float2 v0 = cur[q*3], v1 = cur[q*3+1], v2 = cur[q*3+2];
            csum[0] += v0.x; csum[1] += v0.y;
            csum[2] += v1.x; csum[3] += v1.y;
            csum[4] += v2.x; csum[5] += v2.y;
            cmax[0] = fmaxf(cmax[0], v0.x); cmax[1] = fmaxf(cmax[1], v0.y);
            cmax[2] = fmaxf(cmax[2], v1.x); cmax[3] = fmaxf(cmax[3], v1.y);
            cmax[4] = fmaxf(cmax[4], v2.x); cmax[5] = fmaxf(cmax[5], v2.y);
            ps[q] = (v0.x + v0.y) + (v1.x + v1.y) + (v2.x + v2.y);
            pm[q] = fmaxf(fmaxf(fmaxf(v0.x,v0.y), fmaxf(v1.x,v1.y)), fmaxf(v2.x,v2.y));
        }
        #pragma unroll
        for (int o = 16; o > 0; o >>= 1) {
            #pragma unroll
            for (int q = 0; q < 4; q++) {
                ps[q] += __shfl_xor_sync(0xffffffffu, ps[q], o);
                pm[q] = fmaxf(pm[q], __shfl_xor_sync(0xffffffffu, pm[q], o));
            }
        }
        if (lane < 4) spbase[p + lane] = make_float2(ps[lane] * (1.0f/192.0f), pm[lane]);

        #pragma unroll
        for (int k = 0; k < 12; k++) cur[k] = nxt[k];
        p = pn;
    }

    #pragma unroll
    for (int j = 0; j < 3; j++) {
        int c = 2*(lane + 32*j);
        atomicAdd(&s_sum[c],   csum[2*j]);
        atomicAdd(&s_sum[c+1], csum[2*j+1]);
        atomicMax(&s_max[c],   f2u_ord(cmax[2*j]));
        atomicMax(&s_max[c+1], f2u_ord(cmax[2*j+1]));
    }
    __syncthreads();
    if (threadIdx.x < CDIM) {
        atomicAdd(&g_sum[b*CDIM + threadIdx.x], s_sum[threadIdx.x]);
        atomicMax(&g_maxu[b*CDIM + threadIdx.x], s_max[threadIdx.x]);
    }
}

// ---------------- kernel 2: SE + CBAM-channel MLPs, fused scale ----------------
// grid B, block 192
__global__ void k_mlp(const float* __restrict__ se_w1, const float* __restrict__ se_b1,
                      const float* __restrict__ se_w2, const float* __restrict__ se_b2,
                      const float* __restrict__ mlp_w1, const float* __restrict__ mlp_b1,
                      const float* __restrict__ mlp_w2, const float* __restrict__ mlp_b2) {
    int b = blockIdx.x, t = threadIdx.x;
    __shared__ float avg[CDIM], mx[CDIM], hse[12], ha[24], hm[24];

    avg[t] = g_sum[b*CDIM + t] * (1.0f/(float)HW);
    mx[t]  = u2f_ord(g_maxu[b*CDIM + t]);
    __syncthreads();

    if (t < 12) {
        float a = se_b1[t];
        for (int c = 0; c < CDIM; c++) a += avg[c] * se_w1[c*12 + t];
        hse[t] = swishf(a);
    } else if (t >= 32 && t < 56) {
        int j = t - 32;
        float a = mlp_b1[j], m = mlp_b1[j];
        for (int c = 0; c < CDIM; c++) {
            float w = mlp_w1[c*24 + j];
            a += avg[c]*w; m += mx[c]*w;
        }
        ha[j] = swishf(a); hm[j] = swishf(m);
    }
    __syncthreads();

    float s = se_b2[t];
    #pragma unroll
    for (int j = 0; j < 12; j++) s += hse[j] * se_w2[j*CDIM + t];
    float catt = 2.0f * mlp_b2[t];
    #pragma unroll
    for (int j = 0; j < 24; j++) catt += (ha[j] + hm[j]) * mlp_w2[j*CDIM + t];

    g_scale[b*CDIM + t] = sigm(s) * sigm(catt);
}

// ---------------- kernel 3: fused 7x7 conv + sigmoid + elementwise apply ----
// EXACT R7 structure (measured 93.4us, DRAM=76.8%): grid (H, B), block
// (48, 8) = 384 threads. 7x118 float2 tile of g_sp (L2-hot), 112 threads
// compute the row's spatial attention into smem, then all 384 threads
// stream x -> out with PLAIN float4 loads/stores (R15 showed __ldcs/__stcs
// hurt here: 101.5us, DRAM 70.5%).
__global__ void k_apply(const float* __restrict__ x, float* __restrict__ out,
                        const float* __restrict__ conv_k, const float* __restrict__ conv_b) {
    int b = blockIdx.y, h = blockIdx.x;
    int tid = threadIdx.y * C4 + threadIdx.x;

    __shared__ float2 tile[7][WDIM+6];     // rows h-3..h+3, cols -3..114
    __shared__ float  sa[WDIM];
    __shared__ float2 kk2[49];
    __shared__ float  kb;

    for (int i = tid; i < 7*(WDIM+6); i += 384) {
        int kh = i / (WDIM+6);
        int ww = i - kh*(WDIM+6);
        int gh = h + kh - 3, gw = ww - 3;
        float2 v = make_float2(0.0f, 0.0f);
        if (gh >= 0 && gh < HDIM && gw >= 0 && gw < WDIM)
            v = g_sp[b*HW + gh*WDIM + gw];
        tile[kh][ww] = v;
    }
    if (tid < 49) kk2[tid] = ((const float2*)conv_k)[tid];
    if (tid == 0) kb = conv_b[0];
    __syncthreads();

    if (tid < WDIM) {
        float acc = kb;
        #pragma unroll
        for (int kh = 0; kh < 7; kh++)
            #pragma unroll
            for (int kw = 0; kw < 7; kw++) {
                float2 v = tile[kh][tid+kw];
                float2 k = kk2[kh*7+kw];
                acc += v.x * k.x + v.y * k.y;
            }
        sa[tid] = sigm(acc);
    }
    __syncthreads();

    int c4 = threadIdx.x, ty = threadIdx.y;
    float4 sc = ((const float4*)(g_scale + b*CDIM))[c4];
    const float4* xp = (const float4*)x + (size_t)(b*HW + h*WDIM) * C4;
    float4*       op = (float4*)out     + (size_t)(b*HW + h*WDIM) * C4;

    #pragma unroll 7
    for (int p = ty; p < WDIM; p += 8) {
        float s = sa[p];
        float4 v = xp[p*C4 + c4];
        v.x *= sc.x * s; v.y *= sc.y * s;
        v.z *= sc.z * s; v.w *= sc.w * s;
        op[p*C4 + c4] = v;
    }
}

// ---------------- launch ----------------
extern "C" void kernel_launch(void* const* d_in, const int* in_sizes, int n_in,
                              void* d_out, int out_size) {
    const float* x      = (const float*)d_in[0];
    const float* se_w1  = (const float*)d_in[1];
    const float* se_b1  = (const float*)d_in[2];
    const float* se_w2  = (const float*)d_in[3];
    const float* se_b2  = (const float*)d_in[4];
    const float* mlp_w1 = (const float*)d_in[5];
    const float* mlp_b1 = (const float*)d_in[6];
    const float* mlp_w2 = (const float*)d_in[7];
    const float* mlp_b2 = (const float*)d_in[8];
    const float* conv_k = (const float*)d_in[9];
    const float* conv_b = (const float*)d_in[10];
    float* out = (float*)d_out;

    k_init<<<(BATCH*CDIM + 255)/256, 256>>>();
    k_pool<<<dim3(HDIM/2, BATCH), 256>>>(x);
    k_mlp<<<BATCH, CDIM>>>(se_w1, se_b1, se_w2, se_b2, mlp_w1, mlp_b1, mlp_w2, mlp_b2);
    k_apply<<<dim3(HDIM, BATCH), dim3(C4, 8)>>>(x, out, conv_k, conv_b);
}